// round 8
// baseline (speedup 1.0000x reference)
#include <cuda_runtime.h>
#include <math.h>

// ---------------------------------------------------------------------------
// Problem constants: B=128, T=1024, D=512, H=512, 4H=2048
//   0: sequence_tensor f32 [128,1024,512]
//   1: batch_lengths   int32 (JAX x64 off) or int64 [128], sorted descending
//   2: W_ih f32 [2048,512]   3: W_hh f32 [2048,512]
//   4: b_ih f32 [2048]       5: b_hh f32 [2048]
// Output: concat( out[128,1024,512], h_final[1,128,512], c_final[1,128,512] )
// ---------------------------------------------------------------------------

#define Bsz   128
#define Tsz   1024
#define Dsz   512
#define Hsz   512
#define G4    2048
#define HPAD  516   // padded smem row stride (floats): 16B-aligned, bank-staggered

// Scratch: precomputed input gates  G[t][b][j]  (1 GiB)
__device__ float g_G[(size_t)Tsz * Bsz * G4];
// Double-buffered hidden state h[b][k]
__device__ float g_hbuf[2][Bsz * Hsz];
// Per-btile barrier state (4 btiles, 128B-padded lines)
__device__ __align__(128) unsigned g_bar_cnt4[4][32];
__device__ __align__(128) unsigned g_bar_gen4[4][32];

// ---- packed fp32 helpers (FFMA2 path: PTX fma.rn.f32x2) --------------------
__device__ __forceinline__ unsigned long long pack2(float x, float y) {
    unsigned long long r;
    asm("mov.b64 %0, {%1, %2};" : "=l"(r) : "f"(x), "f"(y));
    return r;
}
__device__ __forceinline__ void unpack2(unsigned long long v, float& x, float& y) {
    asm("mov.b64 {%0, %1}, %2;" : "=f"(x), "=f"(y) : "l"(v));
}
#define FMA2(d, a, b) asm("fma.rn.f32x2 %0, %1, %2, %0;" : "+l"(d) : "l"(a), "l"(b))

// ---- scoped atomics for the software barrier --------------------------------
__device__ __forceinline__ unsigned ld_acquire_gpu(unsigned* p) {
    unsigned v;
    asm volatile("ld.acquire.gpu.u32 %0, [%1];" : "=r"(v) : "l"(p) : "memory");
    return v;
}
__device__ __forceinline__ unsigned ld_relaxed_gpu(unsigned* p) {
    unsigned v;
    asm volatile("ld.relaxed.gpu.u32 %0, [%1];" : "=r"(v) : "l"(p) : "memory");
    return v;
}
__device__ __forceinline__ unsigned atom_add_acqrel_gpu(unsigned* p, unsigned v) {
    unsigned o;
    asm volatile("atom.add.acq_rel.gpu.u32 %0, [%1], %2;"
                 : "=r"(o) : "l"(p), "r"(v) : "memory");
    return o;
}
__device__ __forceinline__ void st_release_gpu(unsigned* p, unsigned v) {
    asm volatile("st.release.gpu.u32 [%0], %1;" :: "l"(p), "r"(v) : "memory");
}
__device__ __forceinline__ void st_relaxed_gpu(unsigned* p, unsigned v) {
    asm volatile("st.relaxed.gpu.u32 [%0], %1;" :: "l"(p), "r"(v) : "memory");
}

// ---- length dtype detection (int32 vs int64) --------------------------------
__device__ __forceinline__ bool lens_is64(const int* p) {
    return (p[1] == 0 && p[3] == 0 && p[5] == 0);
}
__device__ __forceinline__ int load_len(const int* p, bool is64, int b) {
    return is64 ? p[2 * b] : p[b];
}

// ---------------------------------------------------------------------------
// Phase 1: G[t][b][j] = sum_k seq[b][t][k] * W_ih[j][k] + (b_ih[j] + b_hh[j])
// 128x128x16 SGEMM per block, FFMA2 inner product (unchanged from round 7).
// ---------------------------------------------------------------------------
__global__ void __launch_bounds__(256) pregemm_kernel(
    const float* __restrict__ seq,
    const float* __restrict__ Wih,
    const float* __restrict__ bih,
    const float* __restrict__ bhh,
    const int*   __restrict__ lensraw)
{
    __shared__ float As[16][128];
    __shared__ float Bs[16][128];

    const int t   = blockIdx.y;
    const int j0  = blockIdx.x * 128;
    const int tid = threadIdx.x;
    const int tx  = tid & 15;
    const int ty  = tid >> 4;

    const bool is64 = lens_is64(lensraw);
    const bool grpActive = (load_len(lensraw, is64, ty * 8) > t);

    unsigned long long acc2[8][4];
#pragma unroll
    for (int p = 0; p < 4; ++p) {
        const int j = j0 + tx * 8 + 2 * p;
        const unsigned long long bv =
            pack2(bih[j] + bhh[j], bih[j + 1] + bhh[j + 1]);
#pragma unroll
        for (int i = 0; i < 8; ++i) acc2[i][p] = bv;
    }

    const int lm = tid >> 1;
    const int lk = (tid & 1) * 8;
    const float* arow = seq + ((size_t)lm * Tsz + t) * Dsz + lk;
    const float* brow = Wih + (size_t)(j0 + lm) * Dsz + lk;

    for (int k0 = 0; k0 < Dsz; k0 += 16) {
        const float4 av0 = *(const float4*)(arow + k0);
        const float4 av1 = *(const float4*)(arow + k0 + 4);
        const float4 bv0 = *(const float4*)(brow + k0);
        const float4 bv1 = *(const float4*)(brow + k0 + 4);
        As[lk + 0][lm] = av0.x; As[lk + 1][lm] = av0.y;
        As[lk + 2][lm] = av0.z; As[lk + 3][lm] = av0.w;
        As[lk + 4][lm] = av1.x; As[lk + 5][lm] = av1.y;
        As[lk + 6][lm] = av1.z; As[lk + 7][lm] = av1.w;
        Bs[lk + 0][lm] = bv0.x; Bs[lk + 1][lm] = bv0.y;
        Bs[lk + 2][lm] = bv0.z; Bs[lk + 3][lm] = bv0.w;
        Bs[lk + 4][lm] = bv1.x; Bs[lk + 5][lm] = bv1.y;
        Bs[lk + 6][lm] = bv1.z; Bs[lk + 7][lm] = bv1.w;
        __syncthreads();

        if (grpActive) {
#pragma unroll
            for (int kk = 0; kk < 16; ++kk) {
                const float4 a0 = *(const float4*)&As[kk][ty * 8];
                const float4 a1 = *(const float4*)&As[kk][ty * 8 + 4];
                const ulonglong2 bb0 = *(const ulonglong2*)&Bs[kk][tx * 8];
                const ulonglong2 bb1 = *(const ulonglong2*)&Bs[kk][tx * 8 + 4];
                const float a[8] = {a0.x, a0.y, a0.z, a0.w,
                                    a1.x, a1.y, a1.z, a1.w};
#pragma unroll
                for (int i = 0; i < 8; ++i) {
                    const unsigned long long ad = pack2(a[i], a[i]);
                    FMA2(acc2[i][0], ad, bb0.x);
                    FMA2(acc2[i][1], ad, bb0.y);
                    FMA2(acc2[i][2], ad, bb1.x);
                    FMA2(acc2[i][3], ad, bb1.y);
                }
            }
        }
        __syncthreads();
    }

    if (grpActive) {
#pragma unroll
        for (int i = 0; i < 8; ++i) {
            float f0, f1, f2, f3, f4, f5, f6, f7;
            unpack2(acc2[i][0], f0, f1);
            unpack2(acc2[i][1], f2, f3);
            unpack2(acc2[i][2], f4, f5);
            unpack2(acc2[i][3], f6, f7);
            const size_t o = ((size_t)t * Bsz + ty * 8 + i) * G4 + j0 + tx * 8;
            *(float4*)&g_G[o]     = make_float4(f0, f1, f2, f3);
            *(float4*)&g_G[o + 4] = make_float4(f4, f5, f6, f7);
        }
    }
}

// ---------------------------------------------------------------------------
// Per-btile software barrier (32 blocks), release/acquire atomics only.
// ---------------------------------------------------------------------------
__device__ __forceinline__ void tile_barrier(unsigned* cnt, unsigned* gen)
{
    __syncthreads();
    if (threadIdx.x == 0) {
        const unsigned old = ld_relaxed_gpu(gen);
        const unsigned ticket = atom_add_acqrel_gpu(cnt, 1u);
        if (ticket == 31u) {
            st_relaxed_gpu(cnt, 0u);
            st_release_gpu(gen, old + 1u);
        } else {
            while (ld_acquire_gpu(gen) == old) { }
        }
    }
    __syncthreads();
}

__device__ __forceinline__ float sigmf(float x) {
    return __fdividef(1.f, 1.f + __expf(-x));
}
__device__ __forceinline__ float tanh_fast(float x) {
    return 1.f - __fdividef(2.f, __expf(2.f * x) + 1.f);
}

// ---------------------------------------------------------------------------
// Phase 2: persistent recurrence, k-SIMD FFMA2 GEMM.
// 128 blocks = (btile 0..3 [32 rows]) x (ntile 0..31 [16 hidden units]).
// smem: W_s[rc][k] rc = gate*16 + nh_local (64 rows x HPAD),
//       h_s[b][k]  (32 rows x HPAD).  Both direct row copies of the source.
// Warp tile 8 rows x 32 cols: warp_r = wid&3, warp_c = wid>>2;
// lanes: lane_r = lid>>3 (row pair), lane_c = lid&7 (hidden unit).
// Thread: rows (b_r0, b_r0+1), all 4 gates of hidden unit n  ->  thread-local
// LSTM update, c/h state in registers.  Accumulator lanes = (even-k, odd-k).
// ---------------------------------------------------------------------------
__global__ void __launch_bounds__(256, 1) lstm_steps_kernel(
    const float* __restrict__ Whh,
    const int*   __restrict__ lensraw,
    float* __restrict__ out,    // [B,T,H]
    float* __restrict__ hfin,   // [B,H]
    float* __restrict__ cfin)   // [B,H]
{
    extern __shared__ float sm[];
    float* W_s = sm;                   // 64 x HPAD
    float* h_s = sm + 64 * HPAD;       // 32 x HPAD

    const int tid   = threadIdx.x;
    const int bx    = blockIdx.x;          // 0..127
    const int ntile = bx & 31;
    const int btile = bx >> 5;
    const int n0    = ntile * 16;
    const int b0    = btile * 32;
    unsigned* bar_cnt = &g_bar_cnt4[btile][0];
    unsigned* bar_gen = &g_bar_gen4[btile][0];

    // ---- stage W_hh (once): W_s[gate*16 + nhl][k] = Whh[gate*512 + n0+nhl][k]
    {
        const int rc    = tid >> 2;             // 0..63
        const int chunk = tid & 3;              // 0..3 (128 floats each)
        const int gate  = rc >> 4;
        const int nhl   = rc & 15;
        const float* src = Whh + (size_t)(gate * Hsz + n0 + nhl) * Hsz + chunk * 128;
        float* dst = W_s + rc * HPAD + chunk * 128;
#pragma unroll
        for (int i = 0; i < 32; ++i)
            *(float4*)(dst + i * 4) = *(const float4*)(src + i * 4);
    }
    // ---- zero this block's slice of hbuf[0]
#pragma unroll
    for (int q = 0; q < 2; ++q) {
        const int idx = tid + q * 256;
        const int r = idx >> 4, cc = idx & 15;
        g_hbuf[0][(size_t)(b0 + r) * Hsz + n0 + cc] = 0.f;
    }
    // ---- zero-fill out for this btile: rows [b0,b0+32), t in [ntile*32,+32)
    {
        const float4 z4 = make_float4(0.f, 0.f, 0.f, 0.f);
        for (int it = 0; it < 512; ++it) {
            const int p  = it * 2 + (tid >> 7);
            const int r  = p >> 5;
            const int tt = ntile * 32 + (p & 31);
            float4* dst = (float4*)(out + ((size_t)(b0 + r) * Tsz + tt) * Hsz);
            dst[tid & 127] = z4;
        }
    }
    tile_barrier(bar_cnt, bar_gen);

    // ---- GEMM thread mapping
    const int wid    = tid >> 5;
    const int lid    = tid & 31;
    const int warp_r = wid & 3;          // 4 row groups of 8
    const int warp_c = wid >> 2;         // 2 col groups of 8 hidden units
    const int lane_r = lid >> 3;         // 0..3
    const int lane_c = lid & 7;          // 0..7
    const int bloc0  = warp_r * 8 + lane_r * 2;   // even local row
    const int b_r0   = b0 + bloc0;
    const int nh     = warp_c * 8 + lane_c;       // 0..15
    const int n      = n0 + nh;

    const bool is64 = lens_is64(lensraw);
    const int len_tile = load_len(lensraw, is64, b0);
    const int len0 = load_len(lensraw, is64, b_r0);
    const int len1 = load_len(lensraw, is64, b_r0 + 1);

    float hprev0 = 0.f, hprev1 = 0.f;
    float creg0  = 0.f, creg1  = 0.f;

    const float* hp  = h_s + bloc0 * HPAD;         // rows bloc0, bloc0+1
    const float* wp0 = W_s + (0 * 16 + nh) * HPAD; // gate i
    const float* wp1 = W_s + (1 * 16 + nh) * HPAD; // gate f
    const float* wp2 = W_s + (2 * 16 + nh) * HPAD; // gate g
    const float* wp3 = W_s + (3 * 16 + nh) * HPAD; // gate o

    // staging mapping: row = tid>>3 (0..31), 64-float chunk = (tid&7)*64
    const int st_row = tid >> 3;
    const int st_off = (tid & 7) * 64;
    float* st_dst = h_s + st_row * HPAD + st_off;

#pragma unroll 1
    for (int t = 0; t < Tsz; ++t) {
        float* hnext = g_hbuf[(t + 1) & 1];
        const bool tileActive = (t < len_tile);

        if (tileActive) {
            // -- prefetch G[t] (DRAM, independent of h)
            const float* gr0 = g_G + ((size_t)t * Bsz + b_r0) * G4 + n;
            const float gi0 = __ldcg(gr0);
            const float gf0 = __ldcg(gr0 + 512);
            const float gg0 = __ldcg(gr0 + 1024);
            const float go0 = __ldcg(gr0 + 1536);
            const float gi1 = __ldcg(gr0 + G4);
            const float gf1 = __ldcg(gr0 + G4 + 512);
            const float gg1 = __ldcg(gr0 + G4 + 1024);
            const float go1 = __ldcg(gr0 + G4 + 1536);

            // -- stage h tile (direct row copy, L2-coherent)
            {
                const float* src = g_hbuf[t & 1] +
                                   (size_t)(b0 + st_row) * Hsz + st_off;
#pragma unroll
                for (int i = 0; i < 16; ++i)
                    *(float4*)(st_dst + i * 4) =
                        __ldcg((const float4*)(src + i * 4));
            }
            __syncthreads();

            // -- k-SIMD micro-GEMM: acc lanes = (even-k, odd-k) partials
            unsigned long long A00 = 0ull, A01 = 0ull, A02 = 0ull, A03 = 0ull;
            unsigned long long A10 = 0ull, A11 = 0ull, A12 = 0ull, A13 = 0ull;
#pragma unroll 8
            for (int k = 0; k < Hsz; k += 4) {
                const ulonglong2 h0 = *(const ulonglong2*)(hp + k);
                const ulonglong2 h1 = *(const ulonglong2*)(hp + HPAD + k);
                const ulonglong2 w0 = *(const ulonglong2*)(wp0 + k);
                const ulonglong2 w1 = *(const ulonglong2*)(wp1 + k);
                const ulonglong2 w2 = *(const ulonglong2*)(wp2 + k);
                const ulonglong2 w3 = *(const ulonglong2*)(wp3 + k);
                FMA2(A00, h0.x, w0.x); FMA2(A00, h0.y, w0.y);
                FMA2(A01, h0.x, w1.x); FMA2(A01, h0.y, w1.y);
                FMA2(A02, h0.x, w2.x); FMA2(A02, h0.y, w2.y);
                FMA2(A03, h0.x, w3.x); FMA2(A03, h0.y, w3.y);
                FMA2(A10, h1.x, w0.x); FMA2(A10, h1.y, w0.y);
                FMA2(A11, h1.x, w1.x); FMA2(A11, h1.y, w1.y);
                FMA2(A12, h1.x, w2.x); FMA2(A12, h1.y, w2.y);
                FMA2(A13, h1.x, w3.x); FMA2(A13, h1.y, w3.y);
            }
            float e, o2;
            unpack2(A00, e, o2); const float a0i = e + o2;
            unpack2(A01, e, o2); const float a0f = e + o2;
            unpack2(A02, e, o2); const float a0g = e + o2;
            unpack2(A03, e, o2); const float a0o = e + o2;
            unpack2(A10, e, o2); const float a1i = e + o2;
            unpack2(A11, e, o2); const float a1f = e + o2;
            unpack2(A12, e, o2); const float a1g = e + o2;
            unpack2(A13, e, o2); const float a1o = e + o2;

            // -- elementwise LSTM update for 2 batch rows
            {
                const float iv = sigmf(a0i + gi0);
                const float fv = sigmf(a0f + gf0);
                const float gv = tanh_fast(a0g + gg0);
                const float ov = sigmf(a0o + go0);
                const float cn = fv * creg0 + iv * gv;
                const float hn = ov * tanh_fast(cn);
                const bool act = (t < len0);
                creg0  = act ? cn : creg0;
                hprev0 = act ? hn : hprev0;
                if (act) out[((size_t)b_r0 * Tsz + t) * Hsz + n] = hn;
                hnext[(size_t)b_r0 * Hsz + n] = hprev0;
            }
            {
                const float iv = sigmf(a1i + gi1);
                const float fv = sigmf(a1f + gf1);
                const float gv = tanh_fast(a1g + gg1);
                const float ov = sigmf(a1o + go1);
                const float cn = fv * creg1 + iv * gv;
                const float hn = ov * tanh_fast(cn);
                const bool act = (t < len1);
                creg1  = act ? cn : creg1;
                hprev1 = act ? hn : hprev1;
                if (act) out[((size_t)(b_r0 + 1) * Tsz + t) * Hsz + n] = hn;
                hnext[(size_t)(b_r0 + 1) * Hsz + n] = hprev1;
            }
        }
        // inactive tile: outputs already zero-filled, h frozen

        tile_barrier(bar_cnt, bar_gen);   // h handoff within this btile
    }

    // final (frozen) states
    hfin[(size_t)b_r0 * Hsz + n]       = hprev0;
    hfin[(size_t)(b_r0 + 1) * Hsz + n] = hprev1;
    cfin[(size_t)b_r0 * Hsz + n]       = creg0;
    cfin[(size_t)(b_r0 + 1) * Hsz + n] = creg1;
}

// ---------------------------------------------------------------------------
extern "C" void kernel_launch(void* const* d_in, const int* in_sizes, int n_in,
                              void* d_out, int out_size)
{
    (void)in_sizes; (void)n_in; (void)out_size;
    const float* seq  = (const float*)d_in[0];
    const int*   lens = (const int*)d_in[1];
    const float* Wih  = (const float*)d_in[2];
    const float* Whh  = (const float*)d_in[3];
    const float* bih  = (const float*)d_in[4];
    const float* bhh  = (const float*)d_in[5];

    float* outp = (float*)d_out;
    float* hfin = outp + (size_t)Bsz * Tsz * Hsz;
    float* cfin = hfin + (size_t)Bsz * Hsz;

    // dynamic smem: (64 + 32) * HPAD * 4 = 198,144 B
    const int smem_bytes = (64 + 32) * HPAD * 4;
    cudaFuncSetAttribute(lstm_steps_kernel,
                         cudaFuncAttributeMaxDynamicSharedMemorySize, smem_bytes);

    // Phase 1: input-gate GEMM  (16 column tiles x 1024 timesteps)
    dim3 grid1(G4 / 128, Tsz);
    pregemm_kernel<<<grid1, 256>>>(seq, Wih, bih, bhh, lens);

    // Phase 2: persistent recurrence (128 co-resident blocks, btile barriers)
    lstm_steps_kernel<<<128, 256, smem_bytes>>>(Whh, lens, outp, hfin, cfin);
}